// round 14
// baseline (speedup 1.0000x reference)
#include <cuda_runtime.h>
#include <cstdint>

#define NN 2048
#define BS 256
#define NB 8
#define THRESH 0.3f
#define OVERLAP 0.5f
#define NBUCK 512
#define NW 32                 // 2048-bit masks indexed by original n
#define REDGE 16              // register edges per thread
#define POOL 4096             // smem overflow edge pool
#define DYN_BYTES 73728       // dynamic smem for nms kernel

__device__ int g_cnt[NB * 4];                      // zero-init; nms re-zeroes at end
__device__ unsigned long long g_key[NB * 4][NN];   // (score_bits<<32)|(2047-n)
__device__ float2 g_box[NB][NN];

// ---- prep: decode + softmax once per (b,n); warp-aggregated compaction ----
__global__ __launch_bounds__(BS) void prep_kernel(
    const float* __restrict__ loc, const float* __restrict__ cls,
    const float* __restrict__ dflt)
{
    const int b = blockIdx.x >> 3;
    const int n = ((blockIdx.x & 7) << 8) | threadIdx.x;
    const int lane = threadIdx.x & 31;
    const float* locb = loc + (size_t)b * NN * 2;
    const float* clsb = cls + (size_t)b * NN * 5;

    float dc = dflt[2 * n], dw = dflt[2 * n + 1];
    float l0 = locb[2 * n], l1 = locb[2 * n + 1];
    float ctr = dc + l0 * dw;
    float w   = dw * expf(l1);
    g_box[b][n] = make_float2(ctr - 0.5f * w, ctr + 0.5f * w);

    float x0 = clsb[5 * n + 0];
    float x1 = clsb[5 * n + 1];
    float x2 = clsb[5 * n + 2];
    float x3 = clsb[5 * n + 3];
    float x4 = clsb[5 * n + 4];
    float mx = fmaxf(fmaxf(fmaxf(x0, x1), fmaxf(x2, x3)), x4);
    float e1 = expf(x1 - mx), e2 = expf(x2 - mx),
          e3 = expf(x3 - mx), e4 = expf(x4 - mx);
    float sum = expf(x0 - mx) + e1 + e2 + e3 + e4;
    float sc[4] = { e1 / sum, e2 / sum, e3 / sum, e4 / sum };

    #pragma unroll
    for (int c = 0; c < 4; c++) {
        bool v = sc[c] > THRESH;
        unsigned ball = __ballot_sync(0xFFFFFFFFu, v);
        int cnt = __popc(ball);
        if (cnt) {
            int leader = __ffs(ball) - 1;
            int base = 0;
            if (lane == leader) base = atomicAdd(&g_cnt[b * 4 + c], cnt);
            base = __shfl_sync(0xFFFFFFFFu, base, leader);
            if (v) {
                int off = __popc(ball & ((1u << lane) - 1u));
                g_key[b * 4 + c][base + off] =
                    ((unsigned long long)__float_as_uint(sc[c]) << 32)
                    | (unsigned int)(2047 - n);
            }
        }
    }
}

__device__ __forceinline__ unsigned fmap(float f) {
    unsigned u = __float_as_uint(f);
    return u ^ ((u & 0x80000000u) ? 0xFFFFFFFFu : 0x80000000u);
}
__device__ __forceinline__ float funmap(unsigned u) {
    unsigned v = u ^ ((u & 0x80000000u) ? 0x80000000u : 0xFFFFFFFFu);
    return __uint_as_float(v);
}

// ---- nms: one CTA per (b,c) ----
__global__ __launch_bounds__(BS) void nms_kernel(float* __restrict__ out)
{
    extern __shared__ char dyn[];
    unsigned long long* s_tkey = (unsigned long long*)(dyn);           // 16KB
    unsigned long long* s_key  = (unsigned long long*)(dyn + 16384);   // 16KB spatial
    float2*             s_sbox = (float2*)(dyn + 32768);               // 16KB
    float*              s_sc   = (float*)(dyn + 49152);                // 8KB
    unsigned int*       s_pool = (unsigned int*)(dyn + 57344);         // 16KB

    __shared__ unsigned int s_hist[NBUCK];
    __shared__ unsigned int s_bstart[NBUCK + 1];
    __shared__ unsigned int s_boff[NBUCK];
    __shared__ unsigned int s_wsum[8];
    __shared__ unsigned long long s_valid[NW];
    __shared__ unsigned long long s_keep[2][NW];
    __shared__ unsigned long long s_sup[NW];
    __shared__ unsigned int s_minu, s_maxu;
    __shared__ int s_npool, s_over;
    __shared__ int s_chg[2];

    const int bc = blockIdx.x;
    const int b  = bc >> 2;
    const int tid = threadIdx.x;
    const int lane = tid & 31, wid = tid >> 5;
    const int M = g_cnt[bc];

    if (tid == 0) { s_npool = 0; s_over = 0; s_minu = 0xFFFFFFFFu; s_maxu = 0u;
                    s_chg[0] = 0; s_chg[1] = 0; }
    if (tid < NW) s_valid[tid] = 0ull;
    for (int h = tid; h < NBUCK; h += BS) s_hist[h] = 0u;
    __syncthreads();

    // ---- load keys, min/max start, valid mask ----
    for (int s = tid; s < M; s += BS) {
        unsigned long long k = g_key[bc][s];
        s_tkey[s] = k;
        int n = 2047 - (int)(unsigned int)k;
        atomicOr(&s_valid[n >> 6], 1ull << (n & 63));
        unsigned fm = fmap(g_box[b][n].x);
        atomicMin(&s_minu, fm);
        atomicMax(&s_maxu, fm);
    }
    __syncthreads();

    const float mn = funmap(s_minu);
    const float mxs = funmap(s_maxu);
    const float rng = mxs - mn;
    const float scale = (rng > 0.0f) ? ((float)NBUCK / rng) : 0.0f;

    // ---- histogram by start bucket ----
    for (int s = tid; s < M; s += BS) {
        int n = 2047 - (int)(unsigned int)s_tkey[s];
        float st = g_box[b][n].x;
        int bu = (int)fminf((st - mn) * scale, (float)(NBUCK - 1));
        if (bu < 0) bu = 0;
        atomicAdd(&s_hist[bu], 1u);
    }
    __syncthreads();

    // ---- exclusive scan over 512 bins (2 per thread) ----
    {
        unsigned v0 = s_hist[2 * tid], v1 = s_hist[2 * tid + 1];
        unsigned x = v0 + v1;
        #pragma unroll
        for (int o = 1; o < 32; o <<= 1) {
            unsigned y = __shfl_up_sync(0xFFFFFFFFu, x, o);
            if (lane >= o) x += y;
        }
        if (lane == 31) s_wsum[wid] = x;
        __syncthreads();
        if (tid == 0) {
            unsigned acc = 0;
            for (int w2 = 0; w2 < 8; w2++) { unsigned t = s_wsum[w2]; s_wsum[w2] = acc; acc += t; }
            s_bstart[NBUCK] = acc;
        }
        __syncthreads();
        unsigned excl = x + s_wsum[wid] - (v0 + v1);
        s_bstart[2 * tid] = excl;          s_boff[2 * tid] = excl;
        s_bstart[2 * tid + 1] = excl + v0; s_boff[2 * tid + 1] = excl + v0;
    }
    __syncthreads();

    // ---- scatter into spatial (bucket) order ----
    for (int s = tid; s < M; s += BS) {
        unsigned long long k = s_tkey[s];
        int n = 2047 - (int)(unsigned int)k;
        float2 bx = g_box[b][n];
        int bu = (int)fminf((bx.x - mn) * scale, (float)(NBUCK - 1));
        if (bu < 0) bu = 0;
        int pos = atomicAdd(&s_boff[bu], 1u);
        s_key[pos] = k;
        s_sbox[pos] = bx;
    }
    __syncthreads();

    // ---- sparse pair scan -> register edges (+ smem overflow pool) ----
    unsigned eg[REDGE];
    int ne = 0;
    for (int p = tid; p < M; p += BS) {
        float2 bp = s_sbox[p];
        unsigned long long kp = s_key[p];
        int np = 2047 - (int)(unsigned int)kp;
        float lp = bp.y - bp.x;
        int be = (int)fminf((bp.y - mn) * scale, (float)(NBUCK - 1));
        if (be < 0) be = 0;
        int lim = (int)s_bstart[be + 1];
        for (int q = p + 1; q < lim; q++) {
            float2 bq = s_sbox[q];
            float inter = fmaxf(fminf(bp.y, bq.y) - fmaxf(bp.x, bq.x), 0.0f);
            float uni = lp + (bq.y - bq.x) - inter;
            float iou = inter / fmaxf(uni, 1e-12f);
            if (iou > OVERLAP) {
                unsigned long long kq = s_key[q];
                int nq = 2047 - (int)(unsigned int)kq;
                unsigned e = (kp > kq) ? (((unsigned)nq << 16) | (unsigned)np)
                                       : (((unsigned)np << 16) | (unsigned)nq);
                if (ne < REDGE) eg[ne++] = e;
                else {
                    int sl = atomicAdd(&s_npool, 1);
                    if (sl < POOL) s_pool[sl] = e;
                    else s_over = 1;
                }
            }
        }
    }
    // init keep = valid; zero sup for round 0
    if (tid < NW) { s_keep[0][tid] = s_valid[tid]; s_sup[tid] = 0ull; }
    __syncthreads();
    const int npool = (s_npool < POOL) ? s_npool : POOL;
    const int overflow = s_over;

    // ---- Jacobi to the greedy fixpoint (2 barriers/round) ----
    int cb = 0;
    for (int round = 0; round <= M; round++) {
        // edge pass: s_sup was zeroed before the barrier we just crossed
        if (!overflow) {
            for (int e = 0; e < ne; e++) {
                unsigned ed = eg[e];
                int a = ed & 0xffff;
                if ((s_keep[cb][a >> 6] >> (a & 63)) & 1ull) {
                    int wn = ed >> 16;
                    atomicOr(&s_sup[wn >> 6], 1ull << (wn & 63));
                }
            }
            for (int e = tid; e < npool; e += BS) {
                unsigned ed = s_pool[e];
                int a = ed & 0xffff;
                if ((s_keep[cb][a >> 6] >> (a & 63)) & 1ull) {
                    int wn = ed >> 16;
                    atomicOr(&s_sup[wn >> 6], 1ull << (wn & 63));
                }
            }
        } else {
            // exact fallback: re-scan windows each round (never expected)
            for (int p = tid; p < M; p += BS) {
                float2 bp = s_sbox[p];
                unsigned long long kp = s_key[p];
                int np = 2047 - (int)(unsigned int)kp;
                float lp = bp.y - bp.x;
                int be = (int)fminf((bp.y - mn) * scale, (float)(NBUCK - 1));
                if (be < 0) be = 0;
                int lim = (int)s_bstart[be + 1];
                for (int q = p + 1; q < lim; q++) {
                    float2 bq = s_sbox[q];
                    float inter = fmaxf(fminf(bp.y, bq.y) - fmaxf(bp.x, bq.x), 0.0f);
                    float uni = lp + (bq.y - bq.x) - inter;
                    float iou = inter / fmaxf(uni, 1e-12f);
                    if (iou > OVERLAP) {
                        unsigned long long kq = s_key[q];
                        int nq = 2047 - (int)(unsigned int)kq;
                        int a, wn;
                        if (kp > kq) { a = np; wn = nq; } else { a = nq; wn = np; }
                        if ((s_keep[cb][a >> 6] >> (a & 63)) & 1ull)
                            atomicOr(&s_sup[wn >> 6], 1ull << (wn & 63));
                    }
                }
            }
        }
        __syncthreads();

        // recombine + changed flag + zero sup for next round, one barrier
        if (tid < NW) {
            unsigned long long nv = s_valid[tid] & ~s_sup[tid];
            if (nv != s_keep[cb][tid]) s_chg[round & 1] = 1;
            s_keep[cb ^ 1][tid] = nv;
            s_sup[tid] = 0ull;
        }
        if (tid == NW) s_chg[(round + 2) & 1] = 0;   // reset flag for round+2
        __syncthreads();
        cb ^= 1;
        if (!s_chg[round & 1]) break;
    }

    // ---- scatter kept scores by original n ----
    for (int p = tid; p < M; p += BS) {
        unsigned long long k = s_key[p];
        int n = 2047 - (int)(unsigned int)k;
        if ((s_keep[cb][n >> 6] >> (n & 63)) & 1ull)
            s_sc[n] = __uint_as_float((unsigned int)(k >> 32));
    }
    __syncthreads();

    // ---- output (in_range applied AFTER NMS, matching reference) ----
    float* ob = out + (size_t)bc * NN * 3;
    for (int n = tid; n < NN; n += BS) {
        float2 bx = g_box[b][n];
        bool kp = ((s_keep[cb][n >> 6] >> (n & 63)) & 1ull)
                  && (bx.x > -10.0f) && (bx.y < 10.0f);
        ob[3 * n + 0] = kp ? bx.x : 0.0f;
        ob[3 * n + 1] = kp ? bx.y : 0.0f;
        ob[3 * n + 2] = kp ? s_sc[n] : 0.0f;
    }

    // ---- self-restore: leave counters zeroed for the next replay ----
    if (tid == 0) g_cnt[bc] = 0;
}

extern "C" void kernel_launch(void* const* d_in, const int* in_sizes, int n_in,
                              void* d_out, int out_size) {
    const float* loc  = (const float*)d_in[0];  // (8,2048,2)
    const float* cls  = (const float*)d_in[1];  // (8,2048,5)
    const float* dflt = (const float*)d_in[2];  // (2048,2)
    float* out = (float*)d_out;                 // (8,4,2048,3)
    cudaFuncSetAttribute(nms_kernel, cudaFuncAttributeMaxDynamicSharedMemorySize,
                         DYN_BYTES);
    prep_kernel<<<64, BS>>>(loc, cls, dflt);
    nms_kernel<<<32, BS, DYN_BYTES>>>(out);
}